// round 4
// baseline (speedup 1.0000x reference)
#include <cuda_runtime.h>
#include <cuda_bf16.h>

// loss = -(1/B) * sum_b [ 1 / (sum_j sigmoid(x[b,j] - x[b,0]) + 0.5) ]
// B = 32, N = 2048. Only row i=0 of the reference's [B,N,N] pair matrix is
// ever used, so we compute the O(B*N) reduction directly.

static __global__ void rankloss_init(float* out) {
    if (threadIdx.x == 0) out[0] = 0.0f;
}

static __global__ void __launch_bounds__(256) rankloss_kernel(
    const float* __restrict__ x, float* __restrict__ out, int N, float inv_B)
{
    const int b   = blockIdx.x;
    const int tid = threadIdx.x;
    const float* row = x + (size_t)b * N;

    const float x0 = __ldg(row);

    // Each thread reduces N/(256*4) = 2 float4 chunks (N=2048).
    const float4* row4 = reinterpret_cast<const float4*>(row);
    const int n4 = N >> 2;  // 512

    float s = 0.0f;
    #pragma unroll 4
    for (int i = tid; i < n4; i += 256) {
        float4 v = __ldg(row4 + i);
        // sigmoid(v - x0) = 1 / (1 + exp(x0 - v))
        s += __fdividef(1.0f, 1.0f + __expf(x0 - v.x));
        s += __fdividef(1.0f, 1.0f + __expf(x0 - v.y));
        s += __fdividef(1.0f, 1.0f + __expf(x0 - v.z));
        s += __fdividef(1.0f, 1.0f + __expf(x0 - v.w));
    }

    // warp reduce
    #pragma unroll
    for (int o = 16; o > 0; o >>= 1)
        s += __shfl_xor_sync(0xFFFFFFFFu, s, o);

    __shared__ float warp_sums[8];
    const int warp = tid >> 5;
    const int lane = tid & 31;
    if (lane == 0) warp_sums[warp] = s;
    __syncthreads();

    if (warp == 0) {
        float t = (lane < 8) ? warp_sums[lane] : 0.0f;
        #pragma unroll
        for (int o = 4; o > 0; o >>= 1)
            t += __shfl_xor_sync(0xFFFFFFFFu, t, o);
        if (lane == 0) {
            float rr = 1.0f / (t + 0.5f);
            atomicAdd(out, -rr * inv_B);
        }
    }
}

extern "C" void kernel_launch(void* const* d_in, const int* in_sizes, int n_in,
                              void* d_out, int out_size) {
    const float* x = (const float*)d_in[0];
    float* out = (float*)d_out;

    const int total = in_sizes[0];   // B * N = 65536
    const int N = 2048;
    const int B = total / N;         // 32

    rankloss_init<<<1, 32>>>(out);
    rankloss_kernel<<<B, 256>>>(x, out, N, 1.0f / (float)B);
}

// round 5
// speedup vs baseline: 1.0435x; 1.0435x over previous
#include <cuda_runtime.h>
#include <cuda_bf16.h>

// loss = -(1/B) * sum_b [ 1 / (sum_j sigmoid(x[b,j] - x[b,0]) + 0.5) ]
// B = 32, N = 2048. Only row i=0 of the reference's [B,N,N] pair matrix is
// ever used, so we compute the O(B*N) reduction directly.

static __global__ void rankloss_init(float* out) {
    if (threadIdx.x == 0) out[0] = 0.0f;
}

static __global__ void __launch_bounds__(256) rankloss_kernel(
    const float* __restrict__ x, float* __restrict__ out, int N, float inv_B)
{
    const int b   = blockIdx.x;
    const int tid = threadIdx.x;
    const float* row = x + (size_t)b * N;

    const float x0 = __ldg(row);

    // Each thread reduces N/(256*4) = 2 float4 chunks (N=2048).
    const float4* row4 = reinterpret_cast<const float4*>(row);
    const int n4 = N >> 2;  // 512

    float s = 0.0f;
    #pragma unroll 4
    for (int i = tid; i < n4; i += 256) {
        float4 v = __ldg(row4 + i);
        // sigmoid(v - x0) = 1 / (1 + exp(x0 - v))
        s += __fdividef(1.0f, 1.0f + __expf(x0 - v.x));
        s += __fdividef(1.0f, 1.0f + __expf(x0 - v.y));
        s += __fdividef(1.0f, 1.0f + __expf(x0 - v.z));
        s += __fdividef(1.0f, 1.0f + __expf(x0 - v.w));
    }

    // warp reduce
    #pragma unroll
    for (int o = 16; o > 0; o >>= 1)
        s += __shfl_xor_sync(0xFFFFFFFFu, s, o);

    __shared__ float warp_sums[8];
    const int warp = tid >> 5;
    const int lane = tid & 31;
    if (lane == 0) warp_sums[warp] = s;
    __syncthreads();

    if (warp == 0) {
        float t = (lane < 8) ? warp_sums[lane] : 0.0f;
        #pragma unroll
        for (int o = 4; o > 0; o >>= 1)
            t += __shfl_xor_sync(0xFFFFFFFFu, t, o);
        if (lane == 0) {
            float rr = 1.0f / (t + 0.5f);
            atomicAdd(out, -rr * inv_B);
        }
    }
}

extern "C" void kernel_launch(void* const* d_in, const int* in_sizes, int n_in,
                              void* d_out, int out_size) {
    const float* x = (const float*)d_in[0];
    float* out = (float*)d_out;

    const int total = in_sizes[0];   // B * N = 65536
    const int N = 2048;
    const int B = total / N;         // 32

    rankloss_init<<<1, 32>>>(out);
    rankloss_kernel<<<B, 256>>>(x, out, N, 1.0f / (float)B);
}